// round 17
// baseline (speedup 1.0000x reference)
#include <cuda_runtime.h>
#include <cuda_bf16.h>
#include <cuda_fp16.h>
#include <cstdint>

#define BTc 16
#define Nc 1024
#define Dc 128
#define Hc 8
#define HDc 16
#define Mc (BTc*Nc)

// ---- gmem scratch (no allocs allowed) ----
__device__ __half g_q16[(size_t)BTc*Hc*Nc*HDc];   // [slab][n][hd]
__device__ __half g_k16[(size_t)BTc*Hc*Nc*HDc];
__device__ __half g_vt16[(size_t)BTc*Hc*HDc*Nc];  // [slab][hd][n]
__device__ __half g_adjh[(size_t)BTc*Nc*Nc];      // fp16 adj (32MB)
__device__ float g_ctx[(size_t)Mc*Dc];

__device__ __forceinline__ float fast_ex2(float x){ float r; asm("ex2.approx.f32 %0,%1;":"=f"(r):"f"(x)); return r; }
__device__ __forceinline__ uint32_t smem_u32(const void* p){ uint32_t a; asm("{ .reg .u64 t; cvta.to.shared.u64 t, %1; cvt.u32.u64 %0, t; }":"=r"(a):"l"(p)); return a; }
__device__ __forceinline__ uint32_t packbf(float x, float y){
    __nv_bfloat162 t = __floats2bfloat162_rn(x, y);
    return *reinterpret_cast<uint32_t*>(&t);
}
__device__ __forceinline__ uint32_t packh2(float x, float y){
    __half2 t = __floats2half2_rn(x, y);              // .x = low half
    return *reinterpret_cast<uint32_t*>(&t);
}
// bf16 mma (projections)
__device__ __forceinline__ void mma16816(float* d, uint32_t a0,uint32_t a1,uint32_t a2,uint32_t a3,
                                         uint32_t b0,uint32_t b1){
    asm volatile("mma.sync.aligned.m16n8k16.row.col.f32.bf16.bf16.f32 "
        "{%0,%1,%2,%3},{%4,%5,%6,%7},{%8,%9},{%0,%1,%2,%3};"
        : "+f"(d[0]),"+f"(d[1]),"+f"(d[2]),"+f"(d[3])
        : "r"(a0),"r"(a1),"r"(a2),"r"(a3),"r"(b0),"r"(b1));
}
// fp16 mma (attention)
__device__ __forceinline__ void mma16816h(float* d, uint32_t a0,uint32_t a1,uint32_t a2,uint32_t a3,
                                          uint32_t b0,uint32_t b1){
    asm volatile("mma.sync.aligned.m16n8k16.row.col.f32.f16.f16.f32 "
        "{%0,%1,%2,%3},{%4,%5,%6,%7},{%8,%9},{%0,%1,%2,%3};"
        : "+f"(d[0]),"+f"(d[1]),"+f"(d[2]),"+f"(d[3])
        : "r"(a0),"r"(a1),"r"(a2),"r"(a3),"r"(b0),"r"(b1));
}
#define CP16(dst,src) asm volatile("cp.async.ca.shared.global [%0], [%1], 16;"::"r"(dst),"l"(src):"memory")
#define CP_COMMIT()   asm volatile("cp.async.commit_group;":::"memory")
#define CP_WAIT0()    asm volatile("cp.async.wait_group 0;":::"memory")

// attention smem layout (bytes); Q/K rows 24 halfs (48B), V rows 136 halfs (272B), adj rows 136 halfs
#define A_Q 0
#define A_K 12288
#define A_V 24576
#define A_ADJ 33280
#define ADJ_BUF 34816
#define SMEM_ATTN (A_ADJ + 2*ADJ_BUF)   // 102912; x2 CTAs = 205824 <= 228KB

// projection smem (bf16x3 GEMM); tiles stride 136 bf16
#define SPITCH 136
#define P_XH 0
#define P_XL 34816
#define P_WH 69632
#define P_WL 104448
#define P_BIAS 139264
#define SMEM_PROJ 139776

// ============================================================
// Shared bf16x3 GEMM tile: C[128,128] = X @ W^T
// ============================================================
__device__ __forceinline__ void proj_mma_tile(const float* __restrict__ Xg,
                                              const float* __restrict__ Wg,
                                              const float* __restrict__ bias,
                                              char* smc, int m0, float acc[16][4])
{
    int tid = threadIdx.x;
    __nv_bfloat16* Xh = (__nv_bfloat16*)(smc + P_XH);
    __nv_bfloat16* Xl = (__nv_bfloat16*)(smc + P_XL);
    __nv_bfloat16* Wh = (__nv_bfloat16*)(smc + P_WH);
    __nv_bfloat16* Wl = (__nv_bfloat16*)(smc + P_WL);
    float* bias_s = (float*)(smc + P_BIAS);
    if (tid < 128) bias_s[tid] = bias[tid];

    #pragma unroll
    for (int it = 0; it < 16; ++it) {
        int idx = it*256 + tid; int m = idx >> 5, k4 = (idx & 31)*4;
        float4 v = *(const float4*)(Xg + (size_t)(m0+m)*128 + k4);
        uint32_t H0 = packbf(v.x, v.y), H1 = packbf(v.z, v.w);
        float r0 = v.x - __uint_as_float(H0 << 16);
        float r1 = v.y - __uint_as_float(H0 & 0xffff0000u);
        float r2 = v.z - __uint_as_float(H1 << 16);
        float r3 = v.w - __uint_as_float(H1 & 0xffff0000u);
        *(uint2*)(Xh + m*SPITCH + k4) = make_uint2(H0, H1);
        *(uint2*)(Xl + m*SPITCH + k4) = make_uint2(packbf(r0, r1), packbf(r2, r3));
        float4 w = *(const float4*)(Wg + (size_t)m*128 + k4);
        uint32_t G0 = packbf(w.x, w.y), G1 = packbf(w.z, w.w);
        float s0 = w.x - __uint_as_float(G0 << 16);
        float s1 = w.y - __uint_as_float(G0 & 0xffff0000u);
        float s2 = w.z - __uint_as_float(G1 << 16);
        float s3 = w.w - __uint_as_float(G1 & 0xffff0000u);
        *(uint2*)(Wh + m*SPITCH + k4) = make_uint2(G0, G1);
        *(uint2*)(Wl + m*SPITCH + k4) = make_uint2(packbf(s0, s1), packbf(s2, s3));
    }
    __syncthreads();

    int w = tid >> 5, l = tid & 31;
    int g = l >> 2, c2 = (l & 3)*2;
    int m0w = w*16;
    #pragma unroll
    for (int j = 0; j < 16; ++j) { acc[j][0]=0.f; acc[j][1]=0.f; acc[j][2]=0.f; acc[j][3]=0.f; }

    #pragma unroll
    for (int ks = 0; ks < 8; ++ks) {
        int kb = ks*16;
        uint32_t ah0 = *(const uint32_t*)(Xh + (m0w+g)*SPITCH + kb + c2);
        uint32_t ah1 = *(const uint32_t*)(Xh + (m0w+g+8)*SPITCH + kb + c2);
        uint32_t ah2 = *(const uint32_t*)(Xh + (m0w+g)*SPITCH + kb + c2 + 8);
        uint32_t ah3 = *(const uint32_t*)(Xh + (m0w+g+8)*SPITCH + kb + c2 + 8);
        uint32_t al0 = *(const uint32_t*)(Xl + (m0w+g)*SPITCH + kb + c2);
        uint32_t al1 = *(const uint32_t*)(Xl + (m0w+g+8)*SPITCH + kb + c2);
        uint32_t al2 = *(const uint32_t*)(Xl + (m0w+g)*SPITCH + kb + c2 + 8);
        uint32_t al3 = *(const uint32_t*)(Xl + (m0w+g+8)*SPITCH + kb + c2 + 8);
        #pragma unroll
        for (int j = 0; j < 16; ++j) {
            int n0 = 8*j;
            uint32_t bh0 = *(const uint32_t*)(Wh + (n0+g)*SPITCH + kb + c2);
            uint32_t bh1 = *(const uint32_t*)(Wh + (n0+g)*SPITCH + kb + c2 + 8);
            uint32_t bl0 = *(const uint32_t*)(Wl + (n0+g)*SPITCH + kb + c2);
            uint32_t bl1 = *(const uint32_t*)(Wl + (n0+g)*SPITCH + kb + c2 + 8);
            mma16816(acc[j], ah0,ah1,ah2,ah3, bh0,bh1);
            mma16816(acc[j], ah0,ah1,ah2,ah3, bl0,bl1);
            mma16816(acc[j], al0,al1,al2,al3, bh0,bh1);
        }
    }
    __syncthreads();
}

// ============================================================
// Merged QKV projection + adj conversion.
// grid (128, 11): y=0..2 -> Q/K/V GEMM (fp16 out), y=3..10 -> adj f32->fp16
// (1024 conversion CTAs overlap the tensor-bound GEMM CTAs).
// ============================================================
__global__ void __launch_bounds__(256) proj_qkv_kernel(
    const float* __restrict__ x, const float* __restrict__ adj,
    const float* __restrict__ Wq, const float* __restrict__ bq,
    const float* __restrict__ Wk, const float* __restrict__ bk,
    const float* __restrict__ Wv, const float* __restrict__ bv)
{
    extern __shared__ char smc[];
    int sel = blockIdx.y;

    if (sel >= 3) {
        int cid = (sel - 3)*128 + blockIdx.x;    // 0..1023
        const float4* src = (const float4*)adj;
        uint2* dst = (uint2*)g_adjh;
        size_t base = (size_t)cid * 4096;
        #pragma unroll 4
        for (int i = 0; i < 16; ++i) {
            size_t idx = base + (size_t)i*256 + threadIdx.x;
            float4 v = src[idx];
            __half2 a = __floats2half2_rn(v.x, v.y);
            __half2 b = __floats2half2_rn(v.z, v.w);
            dst[idx] = make_uint2(*(uint32_t*)&a, *(uint32_t*)&b);
        }
        return;
    }

    const float* W    = (sel==0)?Wq:(sel==1)?Wk:Wv;
    const float* bias = (sel==0)?bq:(sel==1)?bk:bv;
    float scale = (sel==0)?(0.25f*1.4426950408889634f):1.0f;
    int m0 = blockIdx.x * 128;

    float acc[16][4];
    proj_mma_tile(x, W, bias, smc, m0, acc);

    float* bias_s = (float*)(smc + P_BIAS);
    __half* Sh = (__half*)smc;       // 16384 halfs = 32KB staging
    int tid = threadIdx.x, w = tid >> 5, l = tid & 31;
    int g = l >> 2, c2 = (l & 3)*2;
    int r0 = w*16 + g, r1 = r0 + 8;

    #pragma unroll
    for (int j = 0; j < 16; ++j) {
        int n0 = 8*j;
        #pragma unroll
        for (int e = 0; e < 4; ++e) {
            int col = n0 + c2 + (e & 1);
            int r = (e < 2) ? r0 : r1;
            float v = (acc[j][e] + bias_s[col]) * scale;
            int head = col >> 4, hd = col & 15;
            int off = (sel < 2) ? (head*2048 + r*16 + hd)
                                : (head*2048 + hd*128 + r);
            Sh[off] = __float2half_rn(v);
        }
    }
    __syncthreads();

    int bt = m0 / Nc, nbase = m0 % Nc;
    __half* G = (sel==0)?g_q16:(sel==1)?g_k16:g_vt16;
    const uint4* sh4 = (const uint4*)Sh;
    #pragma unroll
    for (int it = 0; it < 8; ++it) {
        int i4 = it*256 + tid;                 // 0..2047
        int head = i4 >> 8, rem = i4 & 255;    // 256 uint4 (4KB) per head
        if (sel < 2) {
            size_t gbase = (((size_t)(bt*Hc + head))*Nc + nbase)*HDc;
            ((uint4*)(G + gbase))[rem] = sh4[i4];
        } else {
            int hd = rem >> 4, n8 = rem & 15;
            size_t gbase = ((size_t)(bt*Hc + head))*HDc*Nc + (size_t)hd*Nc + nbase;
            ((uint4*)(G + gbase))[n8] = sh4[i4];
        }
    }
}

// ============================================================
// O projection (bf16x3, unchanged)
// ============================================================
__global__ void __launch_bounds__(256) proj_o_kernel(
    const float* __restrict__ Wo, const float* __restrict__ bo, float* __restrict__ out)
{
    extern __shared__ char smc[];
    int m0 = blockIdx.x * 128;
    float acc[16][4];
    proj_mma_tile(g_ctx, Wo, bo, smc, m0, acc);

    float* bias_s = (float*)(smc + P_BIAS);
    float* Sf = (float*)smc;   // [128][132]
    int tid = threadIdx.x, w = tid >> 5, l = tid & 31;
    int g = l >> 2, c2 = (l & 3)*2;
    int r0 = w*16 + g, r1 = r0 + 8;
    #pragma unroll
    for (int j = 0; j < 16; ++j) {
        int n0 = 8*j;
        Sf[r0*132 + n0 + c2]     = acc[j][0] + bias_s[n0 + c2];
        Sf[r0*132 + n0 + c2 + 1] = acc[j][1] + bias_s[n0 + c2 + 1];
        Sf[r1*132 + n0 + c2]     = acc[j][2] + bias_s[n0 + c2];
        Sf[r1*132 + n0 + c2 + 1] = acc[j][3] + bias_s[n0 + c2 + 1];
    }
    __syncthreads();
    #pragma unroll
    for (int it = 0; it < 16; ++it) {
        int i4 = it*256 + tid;
        int row = i4 >> 5, c4 = (i4 & 31)*4;
        *(float4*)(out + (size_t)(m0+row)*128 + c4) = *(const float4*)(Sf + row*132 + c4);
    }
}

// ============================================================
// fp16 flash attention, 2 CTAs/SM: grid 256, each CTA owns 4 q-tiles
// of one (bt,h) slab.  Co-resident CTAs run anti-phase -> tensor pipe
// overlaps the neighbor's epilogue.
// ============================================================
__device__ __forceinline__ void issue_loads(int qt, int ch, int b, int t, uint32_t sb,
    const __half* gq, const __half* gk, const __half* gv, const __half* adjh)
{
    int row = t >> 1, hw = t & 1;
    CP16(sb + A_K + b*6144 + row*48 + hw*16, gk + (ch*128+row)*16 + hw*8);
    int vg = t >> 4, vp = t & 15;
    CP16(sb + A_V + b*4352 + vg*272 + vp*16, gv + vg*1024 + ch*128 + vp*8);
    #pragma unroll
    for (int i = 0; i < 8; ++i) {
        int e = i*256 + t, r2 = e >> 4, q8 = e & 15;   // 128 rows x 16 x 16B
        CP16(sb + A_ADJ + b*ADJ_BUF + r2*272 + q8*16,
             adjh + (size_t)(qt*128 + r2)*1024 + ch*128 + q8*8);
    }
    if (ch == 0) {
        int qb = qt & 1;
        CP16(sb + A_Q + qb*6144 + row*48 + hw*16, gq + (qt*128+row)*16 + hw*8);
    }
    CP_COMMIT();
}

__global__ void __launch_bounds__(256,2) attn_mma_kernel()
{
    extern __shared__ char smc[];
    uint32_t sb = smem_u32(smc);
    int t = threadIdx.x, w = t >> 5, l = t & 31;
    int g = l >> 2, c2 = (l & 3)*2;
    int bid = blockIdx.x;
    int slab = bid >> 1;                // (bt*8 + h)
    int qhalf = bid & 1;                // 0: qt 0-3, 1: qt 4-7
    int bt = slab >> 3;
    int m0 = w*16;
    int qbase = qhalf*4;

    const __half* gq = g_q16 + (size_t)slab*Nc*HDc;
    const __half* gk = g_k16 + (size_t)slab*Nc*HDc;
    const __half* gv = g_vt16 + (size_t)slab*HDc*Nc;
    const __half* adjh = g_adjh + ((size_t)bt << 20);

    uint32_t q0=0,q1=0,q2=0,q3=0;
    float ctx0[4], ctx1[4], sum0 = 0.f, sum1 = 0.f;

    issue_loads(qbase, 0, 0, t, sb, gq, gk, gv, adjh);

    for (int it = 0; it < 32; ++it) {
        CP_WAIT0();
        __syncthreads();
        int qt = qbase + (it >> 3), ch = it & 7, b = it & 1;
        if (it < 31) {
            int nit = it + 1;
            issue_loads(qbase + (nit >> 3), nit & 7, nit & 1, t, sb, gq, gk, gv, adjh);
        }

        const __half* sK = (const __half*)(smc + A_K + b*6144);
        const __half* sV = (const __half*)(smc + A_V + b*4352);
        const __half* sAdj = (const __half*)(smc + A_ADJ + b*ADJ_BUF);

        if (ch == 0) {
            const __half* sQ = (const __half*)(smc + A_Q + (qt&1)*6144);
            q0 = *(const uint32_t*)(sQ + (m0+g)*24 + c2);
            q1 = *(const uint32_t*)(sQ + (m0+g+8)*24 + c2);
            q2 = *(const uint32_t*)(sQ + (m0+g)*24 + c2 + 8);
            q3 = *(const uint32_t*)(sQ + (m0+g+8)*24 + c2 + 8);
            ctx0[0]=ctx0[1]=ctx0[2]=ctx0[3]=0.f;
            ctx1[0]=ctx1[1]=ctx1[2]=ctx1[3]=0.f;
            sum0 = 0.f; sum1 = 0.f;
        }

        // ---- S = Q K^T (fp16 single) ----
        float sacc[16][4];
        #pragma unroll
        for (int j = 0; j < 16; ++j) { sacc[j][0]=0.f; sacc[j][1]=0.f; sacc[j][2]=0.f; sacc[j][3]=0.f; }
        #pragma unroll
        for (int j = 0; j < 16; ++j) {
            int n0 = 8*j;
            uint32_t b0 = *(const uint32_t*)(sK + (n0+g)*24 + c2);
            uint32_t b1 = *(const uint32_t*)(sK + (n0+g)*24 + c2 + 8);
            mma16816h(sacc[j], q0,q1,q2,q3, b0,b1);
        }

        // ---- epilogue: p = ex2(s)*adj, pack fp16 A-frags ----
        uint32_t pA[16], pB[16];
        #pragma unroll
        for (int j = 0; j < 16; ++j) {
            __half2 hA2 = *(const __half2*)(sAdj + (m0+g)*136 + 8*j + c2);
            __half2 hB2 = *(const __half2*)(sAdj + (m0+g+8)*136 + 8*j + c2);
            float2 aA = __half22float2(hA2);
            float2 aB = __half22float2(hB2);
            float p0 = fast_ex2(sacc[j][0]) * aA.x;
            float p1 = fast_ex2(sacc[j][1]) * aA.y;
            float p2 = fast_ex2(sacc[j][2]) * aB.x;
            float p3 = fast_ex2(sacc[j][3]) * aB.y;
            sum0 += p0 + p1; sum1 += p2 + p3;
            pA[j] = packh2(p0, p1);
            pB[j] = packh2(p2, p3);
        }

        // ---- ctx += P V (fp16 single) ----
        #pragma unroll
        for (int kk = 0; kk < 8; ++kk) {
            int k0 = 16*kk;
            uint32_t v0 = *(const uint32_t*)(sV + g*136 + k0 + c2);
            uint32_t v1 = *(const uint32_t*)(sV + g*136 + k0 + c2 + 8);
            uint32_t w0 = *(const uint32_t*)(sV + (g+8)*136 + k0 + c2);
            uint32_t w1 = *(const uint32_t*)(sV + (g+8)*136 + k0 + c2 + 8);
            uint32_t a0 = pA[2*kk], a1 = pB[2*kk], a2 = pA[2*kk+1], a3 = pB[2*kk+1];
            mma16816h(ctx0, a0,a1,a2,a3, v0,v1);
            mma16816h(ctx1, a0,a1,a2,a3, w0,w1);
        }

        if (ch == 7) {
            float s0 = sum0, s1 = sum1;
            s0 += __shfl_xor_sync(0xffffffffu, s0, 1);
            s0 += __shfl_xor_sync(0xffffffffu, s0, 2);
            s1 += __shfl_xor_sync(0xffffffffu, s1, 1);
            s1 += __shfl_xor_sync(0xffffffffu, s1, 2);
            float inv0 = 1.0f / (s0 + 1e-8f), inv1 = 1.0f / (s1 + 1e-8f);
            int qr = qt*128 + m0 + g;
            float* op  = g_ctx + ((size_t)((slab >> 3)*Nc + qr))*Dc + (slab & 7)*HDc;
            float* op2 = op + 8*Dc;
            float2 o;
            o.x = ctx0[0]*inv0; o.y = ctx0[1]*inv0; *(float2*)(op + c2) = o;
            o.x = ctx1[0]*inv0; o.y = ctx1[1]*inv0; *(float2*)(op + 8 + c2) = o;
            o.x = ctx0[2]*inv1; o.y = ctx0[3]*inv1; *(float2*)(op2 + c2) = o;
            o.x = ctx1[2]*inv1; o.y = ctx1[3]*inv1; *(float2*)(op2 + 8 + c2) = o;
        }
    }
}

// ============================================================
extern "C" void kernel_launch(void* const* d_in, const int* in_sizes, int n_in,
                              void* d_out, int out_size)
{
    const float* x   = (const float*)d_in[0];
    const float* adj = (const float*)d_in[1];
    const float* Wq  = (const float*)d_in[2];
    const float* bq  = (const float*)d_in[3];
    const float* Wk  = (const float*)d_in[4];
    const float* bk  = (const float*)d_in[5];
    const float* Wv  = (const float*)d_in[6];
    const float* bv  = (const float*)d_in[7];
    const float* Wo  = (const float*)d_in[8];
    const float* bo  = (const float*)d_in[9];
    float* out = (float*)d_out;

    cudaFuncSetAttribute(proj_qkv_kernel, cudaFuncAttributeMaxDynamicSharedMemorySize, SMEM_PROJ);
    cudaFuncSetAttribute(proj_o_kernel,   cudaFuncAttributeMaxDynamicSharedMemorySize, SMEM_PROJ);
    cudaFuncSetAttribute(attn_mma_kernel, cudaFuncAttributeMaxDynamicSharedMemorySize, SMEM_ATTN);

    dim3 gqkv(Mc/128, 11);   // y=0..2: Q/K/V GEMM; y=3..10: adj f32->fp16 (1024 CTAs, overlapped)
    proj_qkv_kernel<<<gqkv, 256, SMEM_PROJ>>>(x, adj, Wq, bq, Wk, bk, Wv, bv);
    attn_mma_kernel<<<BTc*Hc*2, 256, SMEM_ATTN>>>();
    proj_o_kernel<<<Mc/128, 256, SMEM_PROJ>>>(Wo, bo, out);
}